// round 5
// baseline (speedup 1.0000x reference)
#include <cuda_runtime.h>
#include <cstdint>
#include <cstddef>

#define BATCH 64
#define INF   1024
#define OUTF  1024
#define NEXP  8
#define HID   8

// c_t[e][b] = sum_f att[b,f] * align_conv[f,e]
__device__ float g_c[NEXP * BATCH];

// split-K partial outputs: [SPLITS][BATCH][OUTF]  (16 MB static scratch)
#define NTILE  128
#define KB     16
#define KCTA   128
#define NSTG   (KCTA / KB)
#define SPLITS (NEXP * INF / KCTA)        /* 64 */
__device__ float g_part[SPLITS * BATCH * OUTF];

// ---------------------------------------------------------------------------
// packed fp32x2 helpers (FFMA2 is PTX-only on sm_103a)
// ---------------------------------------------------------------------------
__device__ __forceinline__ unsigned long long f32x2_dup(float a) {
    unsigned long long r;
    asm("mov.b64 %0, {%1, %1};" : "=l"(r) : "f"(a));
    return r;
}
__device__ __forceinline__ unsigned long long ffma2(unsigned long long a,
                                                    unsigned long long b,
                                                    unsigned long long c) {
    unsigned long long d;
    asm("fma.rn.f32x2 %0, %1, %2, %3;" : "=l"(d) : "l"(a), "l"(b), "l"(c));
    return d;
}
__device__ __forceinline__ float2 f32x2_unpack(unsigned long long v) {
    float2 r;
    asm("mov.b64 {%0, %1}, %2;" : "=f"(r.x), "=f"(r.y) : "l"(v));
    return r;
}

// ---------------------------------------------------------------------------
// Gating: one block per batch sample. pooled-mean -> tanh RNN step -> relu ->
// linear -> softmax -> fold align_conv:  c[b,e] = sum_f att[b,f]*align[f,e]
// ---------------------------------------------------------------------------
__global__ void gate_kernel(const float* __restrict__ x,
                            const float* __restrict__ align_conv,
                            const float* __restrict__ W_ih,
                            const float* __restrict__ b_ih,
                            const float* __restrict__ b_hh,
                            const float* __restrict__ W_att,
                            const float* __restrict__ b_att)
{
    const int b   = blockIdx.x;
    const int tid = threadIdx.x;
    __shared__ float red[8];

    const float* xr = x + (size_t)b * INF;
    float s = 0.f;
#pragma unroll
    for (int i = 0; i < INF / 256; i++) s += xr[tid + i * 256];
#pragma unroll
    for (int o = 16; o > 0; o >>= 1) s += __shfl_xor_sync(0xffffffffu, s, o);
    if ((tid & 31) == 0) red[tid >> 5] = s;
    __syncthreads();

    if (tid == 0) {
        float tot = 0.f;
#pragma unroll
        for (int wdx = 0; wdx < 8; wdx++) tot += red[wdx];
        const float pooled = tot * (1.0f / INF);

        float r[HID];
#pragma unroll
        for (int j = 0; j < HID; j++)
            r[j] = fmaxf(tanhf(pooled * W_ih[j] + b_ih[j] + b_hh[j]), 0.f);

        float lg[NEXP];
        float mx = -1e30f;
#pragma unroll
        for (int e = 0; e < NEXP; e++) {
            float v = b_att[e];
#pragma unroll
            for (int j = 0; j < HID; j++) v += r[j] * W_att[e * HID + j];
            lg[e] = v;
            mx = fmaxf(mx, v);
        }
        float sum = 0.f;
#pragma unroll
        for (int e = 0; e < NEXP; e++) { lg[e] = expf(lg[e] - mx); sum += lg[e]; }
        const float inv = 1.f / sum;

#pragma unroll
        for (int e2 = 0; e2 < NEXP; e2++) {
            float c = 0.f;
#pragma unroll
            for (int f = 0; f < NEXP; f++) c += (lg[f] * inv) * align_conv[f * NEXP + e2];
            g_c[e2 * BATCH + b] = c;
        }
    }
}

// ---------------------------------------------------------------------------
// GEMM split-K: part[kz][b][o] = sum_{k in chunk} (c[b,e]*x[b,i]) * w[e,o,i]
//   CTA tile: M=64 x N=128, K=128.  grid = (8 n-tiles, 64 k-splits) = 512 CTAs
//   (~3.5 CTAs/SM resident -> 24 warps/SM, enough to saturate the fma pipe).
//   kz: e = kz>>3, i0 = (kz&7)*128.
//   Epilogue: plain STG.128 into g_part (no atomics, no zero-init needed).
// ---------------------------------------------------------------------------
#define AS_S  68
#define BS_S  132

__global__ void __launch_bounds__(256, 3) gemm_kernel(const float* __restrict__ x,
                                                      const float* __restrict__ w)
{
    __shared__ __align__(16) float As[2][KB][AS_S];   // [k][m], scaled by c[m,e]
    __shared__ __align__(16) float Bs[2][KB][BS_S];   // [k][n]

    const int tid  = threadIdx.x;
    const int tmid = tid & 7;
    const int tnid = tid >> 3;
    const int nt0  = blockIdx.x * NTILE;
    const int kz   = blockIdx.y;
    const int e    = kz >> 3;
    const int i0   = (kz & 7) * KCTA;

    const float* xb = x + i0;
    const float* wb = w + ((size_t)e << 20) + (size_t)nt0 * INF + i0;

    // loader indices: 1 float4 of A + 2 float4 of B per thread per stage
    const int am  = tid >> 2;   // 0..63 : A row (batch) and B row (n, n+64)
    const int akq = tid & 3;    // float4 slot along k
    const float cs = g_c[e * BATCH + am];

    unsigned long long acc[8][2];
#pragma unroll
    for (int i = 0; i < 8; i++) { acc[i][0] = 0ull; acc[i][1] = 0ull; }

    float4 aV, bV0, bV1;

    // prologue: load + store stage 0
    aV  = *(const float4*)(xb + (size_t)am * INF + akq * 4);
    bV0 = *(const float4*)(wb + (size_t)am * INF + akq * 4);
    bV1 = *(const float4*)(wb + (size_t)(am + 64) * INF + akq * 4);
    {
        const int k4 = akq * 4;
        As[0][k4 + 0][am] = aV.x * cs;
        As[0][k4 + 1][am] = aV.y * cs;
        As[0][k4 + 2][am] = aV.z * cs;
        As[0][k4 + 3][am] = aV.w * cs;
        Bs[0][k4 + 0][am] = bV0.x;
        Bs[0][k4 + 1][am] = bV0.y;
        Bs[0][k4 + 2][am] = bV0.z;
        Bs[0][k4 + 3][am] = bV0.w;
        Bs[0][k4 + 0][am + 64] = bV1.x;
        Bs[0][k4 + 1][am + 64] = bV1.y;
        Bs[0][k4 + 2][am + 64] = bV1.z;
        Bs[0][k4 + 3][am + 64] = bV1.w;
    }
    __syncthreads();

    for (int kb = 0; kb < NSTG; kb++) {
        const int cur = kb & 1;

        if (kb + 1 < NSTG) {
            const int koff = (kb + 1) * KB + akq * 4;
            aV  = *(const float4*)(xb + (size_t)am * INF + koff);
            bV0 = *(const float4*)(wb + (size_t)am * INF + koff);
            bV1 = *(const float4*)(wb + (size_t)(am + 64) * INF + koff);
        }

#pragma unroll
        for (int kk = 0; kk < KB; kk++) {
            const float4 a1 = *(const float4*)&As[cur][kk][4 * tmid];
            const float4 a2 = *(const float4*)&As[cur][kk][32 + 4 * tmid];
            const unsigned long long b0 = *(const unsigned long long*)&Bs[cur][kk][4 * tnid];
            const unsigned long long b1 = *(const unsigned long long*)&Bs[cur][kk][4 * tnid + 2];

            unsigned long long ap0 = f32x2_dup(a1.x);
            unsigned long long ap1 = f32x2_dup(a1.y);
            unsigned long long ap2 = f32x2_dup(a1.z);
            unsigned long long ap3 = f32x2_dup(a1.w);
            unsigned long long ap4 = f32x2_dup(a2.x);
            unsigned long long ap5 = f32x2_dup(a2.y);
            unsigned long long ap6 = f32x2_dup(a2.z);
            unsigned long long ap7 = f32x2_dup(a2.w);

            acc[0][0] = ffma2(ap0, b0, acc[0][0]);  acc[0][1] = ffma2(ap0, b1, acc[0][1]);
            acc[1][0] = ffma2(ap1, b0, acc[1][0]);  acc[1][1] = ffma2(ap1, b1, acc[1][1]);
            acc[2][0] = ffma2(ap2, b0, acc[2][0]);  acc[2][1] = ffma2(ap2, b1, acc[2][1]);
            acc[3][0] = ffma2(ap3, b0, acc[3][0]);  acc[3][1] = ffma2(ap3, b1, acc[3][1]);
            acc[4][0] = ffma2(ap4, b0, acc[4][0]);  acc[4][1] = ffma2(ap4, b1, acc[4][1]);
            acc[5][0] = ffma2(ap5, b0, acc[5][0]);  acc[5][1] = ffma2(ap5, b1, acc[5][1]);
            acc[6][0] = ffma2(ap6, b0, acc[6][0]);  acc[6][1] = ffma2(ap6, b1, acc[6][1]);
            acc[7][0] = ffma2(ap7, b0, acc[7][0]);  acc[7][1] = ffma2(ap7, b1, acc[7][1]);
        }

        if (kb + 1 < NSTG) {
            const int nb = cur ^ 1;
            const int k4 = akq * 4;
            As[nb][k4 + 0][am] = aV.x * cs;
            As[nb][k4 + 1][am] = aV.y * cs;
            As[nb][k4 + 2][am] = aV.z * cs;
            As[nb][k4 + 3][am] = aV.w * cs;
            Bs[nb][k4 + 0][am] = bV0.x;
            Bs[nb][k4 + 1][am] = bV0.y;
            Bs[nb][k4 + 2][am] = bV0.z;
            Bs[nb][k4 + 3][am] = bV0.w;
            Bs[nb][k4 + 0][am + 64] = bV1.x;
            Bs[nb][k4 + 1][am + 64] = bV1.y;
            Bs[nb][k4 + 2][am + 64] = bV1.z;
            Bs[nb][k4 + 3][am + 64] = bV1.w;
        }
        __syncthreads();
    }

    // epilogue: plain vector stores of this split's partial tile (no atomics)
    float* part = g_part + (size_t)kz * (BATCH * OUTF);
#pragma unroll
    for (int mi = 0; mi < 8; mi++) {
        const int m = (mi < 4) ? (4 * tmid + mi) : (32 + 4 * tmid + (mi - 4));
        const float2 v0 = f32x2_unpack(acc[mi][0]);
        const float2 v1 = f32x2_unpack(acc[mi][1]);
        float4 v; v.x = v0.x; v.y = v0.y; v.z = v1.x; v.w = v1.y;
        *(float4*)(part + (size_t)m * OUTF + nt0 + 4 * tnid) = v;
    }
}

// ---------------------------------------------------------------------------
// Split-K reduction: y = sum over SPLITS of g_part. 16384 float4 outputs.
// grid 128 x block 128 -> one float4 per thread, 64-deep sum with 4-way MLP.
// ---------------------------------------------------------------------------
__global__ void __launch_bounds__(128) reduce_kernel(float* __restrict__ y)
{
    const int i = blockIdx.x * 128 + threadIdx.x;   // 0..16383
    const float4* p = (const float4*)g_part;

    float4 a0 = make_float4(0.f, 0.f, 0.f, 0.f);
    float4 a1 = make_float4(0.f, 0.f, 0.f, 0.f);
    float4 a2 = make_float4(0.f, 0.f, 0.f, 0.f);
    float4 a3 = make_float4(0.f, 0.f, 0.f, 0.f);

#pragma unroll
    for (int s = 0; s < SPLITS; s += 4) {
        const float4 v0 = p[(size_t)(s + 0) * 16384 + i];
        const float4 v1 = p[(size_t)(s + 1) * 16384 + i];
        const float4 v2 = p[(size_t)(s + 2) * 16384 + i];
        const float4 v3 = p[(size_t)(s + 3) * 16384 + i];
        a0.x += v0.x; a0.y += v0.y; a0.z += v0.z; a0.w += v0.w;
        a1.x += v1.x; a1.y += v1.y; a1.z += v1.z; a1.w += v1.w;
        a2.x += v2.x; a2.y += v2.y; a2.z += v2.z; a2.w += v2.w;
        a3.x += v3.x; a3.y += v3.y; a3.z += v3.z; a3.w += v3.w;
    }
    float4 r;
    r.x = (a0.x + a1.x) + (a2.x + a3.x);
    r.y = (a0.y + a1.y) + (a2.y + a3.y);
    r.z = (a0.z + a1.z) + (a2.z + a3.z);
    r.w = (a0.w + a1.w) + (a2.w + a3.w);
    ((float4*)y)[i] = r;
}

// ---------------------------------------------------------------------------
extern "C" void kernel_launch(void* const* d_in, const int* in_sizes, int n_in,
                              void* d_out, int out_size)
{
    (void)in_sizes; (void)n_in; (void)out_size;
    const float* x          = (const float*)d_in[0];
    const float* weight     = (const float*)d_in[1];
    const float* align_conv = (const float*)d_in[2];
    const float* W_ih       = (const float*)d_in[3];
    // d_in[4] = W_hh : unused (h0 == 0)
    const float* b_ih       = (const float*)d_in[5];
    const float* b_hh       = (const float*)d_in[6];
    const float* W_att      = (const float*)d_in[7];
    const float* b_att      = (const float*)d_in[8];
    float* y = (float*)d_out;

    gate_kernel<<<BATCH, 256>>>(x, align_conv, W_ih, b_ih, b_hh, W_att, b_att);
    dim3 grid(OUTF / NTILE, SPLITS);
    gemm_kernel<<<grid, 256>>>(x, weight);
    reduce_kernel<<<128, 128>>>(y);
}

// round 8
// speedup vs baseline: 2.8137x; 2.8137x over previous
#include <cuda_runtime.h>
#include <cuda_fp16.h>
#include <cstdint>
#include <cstddef>

#define BATCH 64
#define INF   1024
#define OUTF  1024
#define NEXP  8
#define HID   8
#define SPLITS 16

// c[e][b] = sum_f att[b,f] * align_conv[f,e]
__device__ float g_c[NEXP * BATCH];
// split-K partials [kz][o][b]  (4 MB static scratch)
__device__ float g_part[SPLITS * OUTF * BATCH];

// ---------------------------------------------------------------------------
// arch-agnostic tensor-core helpers (sm_80+ PTX: valid at target sm_103)
// ---------------------------------------------------------------------------
__device__ __forceinline__ uint32_t smem_u32(const void* p) {
    uint32_t a;
    asm("{ .reg .u64 t; cvta.to.shared.u64 t, %1; cvt.u32.u64 %0, t; }"
        : "=r"(a) : "l"(p));
    return a;
}

__device__ __forceinline__ void ldsm4(uint32_t* r, uint32_t addr) {
    asm volatile("ldmatrix.sync.aligned.m8n8.x4.shared.b16 {%0,%1,%2,%3}, [%4];"
                 : "=r"(r[0]), "=r"(r[1]), "=r"(r[2]), "=r"(r[3]) : "r"(addr));
}

__device__ __forceinline__ void mma16816(float* d, const uint32_t* a,
                                         uint32_t b0, uint32_t b1) {
    asm volatile(
        "mma.sync.aligned.m16n8k16.row.col.f32.f16.f16.f32 "
        "{%0,%1,%2,%3}, {%4,%5,%6,%7}, {%8,%9}, {%0,%1,%2,%3};"
        : "+f"(d[0]), "+f"(d[1]), "+f"(d[2]), "+f"(d[3])
        : "r"(a[0]), "r"(a[1]), "r"(a[2]), "r"(a[3]), "r"(b0), "r"(b1));
}

__device__ __forceinline__ uint32_t h2bits(float a, float b) {
    __half2 h = __floats2half2_rn(a, b);   // low = a, high = b (k-order)
    return *reinterpret_cast<uint32_t*>(&h);
}

// ---------------------------------------------------------------------------
// Gating: grid 64 (one block per batch sample), 256 threads.
// float4 mean-reduce; tail parallelized over 8 lanes (one per expert):
// tanh-RNN -> relu -> linear -> softmax (shfl over 8 lanes) -> align fold.
// ---------------------------------------------------------------------------
__global__ void __launch_bounds__(256) gate_kernel(
    const float* __restrict__ x,
    const float* __restrict__ align_conv,
    const float* __restrict__ W_ih,
    const float* __restrict__ b_ih,
    const float* __restrict__ b_hh,
    const float* __restrict__ W_att,
    const float* __restrict__ b_att)
{
    const int b   = blockIdx.x;
    const int tid = threadIdx.x;
    __shared__ float red[8];

    float4 v = ((const float4*)(x + (size_t)b * INF))[tid];
    float s = (v.x + v.y) + (v.z + v.w);
#pragma unroll
    for (int o = 16; o > 0; o >>= 1) s += __shfl_xor_sync(0xffffffffu, s, o);
    if ((tid & 31) == 0) red[tid >> 5] = s;
    __syncthreads();

    if (tid < 8) {
        float t8 = red[tid];
        t8 += __shfl_xor_sync(0xffu, t8, 1);
        t8 += __shfl_xor_sync(0xffu, t8, 2);
        t8 += __shfl_xor_sync(0xffu, t8, 4);
        const float pooled = t8 * (1.0f / INF);

        const int e = tid;
        float lg = b_att[e];
#pragma unroll
        for (int j = 0; j < HID; j++) {
            float rj = fmaxf(tanhf(pooled * W_ih[j] + b_ih[j] + b_hh[j]), 0.f);
            lg += rj * W_att[e * HID + j];
        }
        float mx = lg;
        mx = fmaxf(mx, __shfl_xor_sync(0xffu, mx, 1));
        mx = fmaxf(mx, __shfl_xor_sync(0xffu, mx, 2));
        mx = fmaxf(mx, __shfl_xor_sync(0xffu, mx, 4));
        float p = expf(lg - mx);
        float ssum = p;
        ssum += __shfl_xor_sync(0xffu, ssum, 1);
        ssum += __shfl_xor_sync(0xffu, ssum, 2);
        ssum += __shfl_xor_sync(0xffu, ssum, 4);
        p /= ssum;

        float c = 0.f;
#pragma unroll
        for (int f = 0; f < NEXP; f++)
            c += __shfl_sync(0xffu, p, f) * align_conv[f * NEXP + e];
        g_c[e * BATCH + b] = c;
    }
}

// ---------------------------------------------------------------------------
// HMMA GEMM: part[kz][o][b] = sum_{i in chunk} w[e,o,i] * (c[b,e]*x[b,i])
//   fp16 operands, fp32 accum (mma.sync m16n8k16).
//   CTA: M=128 (o), N=64 (b); grid = (8 o-tiles, 16 = 8 experts x 2 i-halves).
//   K=512/CTA in 8 chunks of 64; double-buffered 24KB stages.
//   SMEM tiles (fp16): A[o 128][k 64] (16KB), B[b 64][k 64] (8KB), both
//   128B rows with the 16B-granular XOR swizzle -> conflict-free ldmatrix.
//   Warp tile m32 x n32 (warps: 4 along M x 2 along N).
// ---------------------------------------------------------------------------
#define KC       64
#define NCH      8
#define A_BYTES  16384
#define STG      24576
#define SMEM_DYN (2 * STG)

__global__ void __launch_bounds__(256) gemm_hmma(const float* __restrict__ x,
                                                 const float* __restrict__ w)
{
    extern __shared__ __align__(16) uint8_t sm[];
    const int tid = threadIdx.x;
    const int wid = tid >> 5;
    const int lid = tid & 31;
    const int o0  = blockIdx.x * 128;
    const int kz  = blockIdx.y;
    const int e   = kz >> 1;
    const int i0  = (kz & 1) * 512;

    const float* wbase = w + ((size_t)e << 20) + (size_t)o0 * INF + i0;
    const float* xbase = x + i0;

    const int m0 = (wid & 3) * 32;     // warp M offset
    const int n0 = (wid >> 2) * 32;    // warp N offset

    float d[2][4][4];
#pragma unroll
    for (int i = 0; i < 2; i++)
#pragma unroll
        for (int j = 0; j < 4; j++)
#pragma unroll
            for (int k = 0; k < 4; k++) d[i][j][k] = 0.f;

    // loader: A 8 float4/thread, B 4 float4/thread per chunk
    float cs[4];
#pragma unroll
    for (int r = 0; r < 4; r++)
        cs[r] = g_c[e * BATCH + ((tid + (r << 8)) >> 4)];

    float4 av[8], bv[4];
    const uint32_t smb = smem_u32(sm);

    // ---- prologue: load + store stage 0 ----
    {
        const float4* ws = (const float4*)wbase;
        const float4* xs = (const float4*)xbase;
#pragma unroll
        for (int r = 0; r < 8; r++) {
            int g = tid + (r << 8);
            av[r] = ws[(g >> 4) * 256 + (g & 15)];
        }
#pragma unroll
        for (int r = 0; r < 4; r++) {
            int g = tid + (r << 8);
            bv[r] = xs[(g >> 4) * 256 + (g & 15)];
        }
    }

#define STORE_STAGE(sidx) do {                                                 \
    uint8_t* stg = sm + (sidx) * STG;                                          \
    _Pragma("unroll")                                                          \
    for (int r = 0; r < 8; r++) {                                              \
        int g = tid + (r << 8);                                                \
        uint32_t off = (uint32_t)((g >> 4) * 128 + (g & 15) * 8);              \
        off ^= (off >> 3) & 0x70u;                                             \
        uint2 pv; pv.x = h2bits(av[r].x, av[r].y);                             \
        pv.y = h2bits(av[r].z, av[r].w);                                       \
        *(uint2*)(stg + off) = pv;                                             \
    }                                                                          \
    _Pragma("unroll")                                                          \
    for (int r = 0; r < 4; r++) {                                              \
        int g = tid + (r << 8);                                                \
        float c4 = cs[r];                                                      \
        uint32_t off = (uint32_t)((g >> 4) * 128 + (g & 15) * 8);              \
        off ^= (off >> 3) & 0x70u;                                             \
        uint2 pv; pv.x = h2bits(bv[r].x * c4, bv[r].y * c4);                   \
        pv.y = h2bits(bv[r].z * c4, bv[r].w * c4);                             \
        *(uint2*)(stg + A_BYTES + off) = pv;                                   \
    }                                                                          \
} while (0)

    STORE_STAGE(0);
    __syncthreads();

    for (int kc = 0; kc < NCH; kc++) {
        const int cur = kc & 1;

        if (kc + 1 < NCH) {
            const float4* ws = (const float4*)(wbase + (kc + 1) * KC);
            const float4* xs = (const float4*)(xbase + (kc + 1) * KC);
#pragma unroll
            for (int r = 0; r < 8; r++) {
                int g = tid + (r << 8);
                av[r] = ws[(g >> 4) * 256 + (g & 15)];
            }
#pragma unroll
            for (int r = 0; r < 4; r++) {
                int g = tid + (r << 8);
                bv[r] = xs[(g >> 4) * 256 + (g & 15)];
            }
        }

        // ---- compute on stage `cur` ----
        const uint32_t sb = smb + cur * STG;
#pragma unroll
        for (int ks = 0; ks < 4; ks++) {
            uint32_t afr[2][4], bfr[2][4];
#pragma unroll
            for (int mf = 0; mf < 2; mf++) {
                uint32_t row = (uint32_t)(m0 + mf * 16 + (lid & 15));
                uint32_t kg  = (uint32_t)(ks * 2 + (lid >> 4));
                uint32_t off = row * 128 + kg * 16;
                off ^= (off >> 3) & 0x70u;
                ldsm4(afr[mf], sb + off);
            }
#pragma unroll
            for (int nh = 0; nh < 2; nh++) {
                uint32_t nrow = (uint32_t)(n0 + nh * 16 + (lid & 7) + ((lid >> 4) << 3));
                uint32_t kg   = (uint32_t)(ks * 2 + ((lid >> 3) & 1));
                uint32_t off  = nrow * 128 + kg * 16;
                off ^= (off >> 3) & 0x70u;
                ldsm4(bfr[nh], sb + A_BYTES + off);
            }
#pragma unroll
            for (int mf = 0; mf < 2; mf++) {
                mma16816(d[mf][0], afr[mf], bfr[0][0], bfr[0][1]);
                mma16816(d[mf][1], afr[mf], bfr[0][2], bfr[0][3]);
                mma16816(d[mf][2], afr[mf], bfr[1][0], bfr[1][1]);
                mma16816(d[mf][3], afr[mf], bfr[1][2], bfr[1][3]);
            }
        }

        __syncthreads();
        if (kc + 1 < NCH) {
            STORE_STAGE(cur ^ 1);
            __syncthreads();
        }
    }

    // ---- epilogue: STG.64 partials to g_part[kz][o][b] ----
    float* part = g_part + (size_t)kz * (OUTF * BATCH);
    const int tg = lid >> 2;
    const int tc = (lid & 3) * 2;
#pragma unroll
    for (int mf = 0; mf < 2; mf++) {
#pragma unroll
        for (int nf = 0; nf < 4; nf++) {
            const int ol = m0 + mf * 16 + tg;
            const int bb = n0 + nf * 8 + tc;
            float2 v0; v0.x = d[mf][nf][0]; v0.y = d[mf][nf][1];
            float2 v1; v1.x = d[mf][nf][2]; v1.y = d[mf][nf][3];
            *(float2*)(part + (size_t)(o0 + ol) * BATCH + bb) = v0;
            *(float2*)(part + (size_t)(o0 + ol + 8) * BATCH + bb) = v1;
        }
    }
}

// ---------------------------------------------------------------------------
// Split-K reduce + transpose: y[b][o] = sum_kz part[kz][o][b].
// Coalesced loads (b fastest); 4 MB is L2-resident.
// ---------------------------------------------------------------------------
__global__ void __launch_bounds__(256) reduce_kernel(float* __restrict__ y)
{
    const int gid = blockIdx.x * 256 + threadIdx.x;   // 0..65535
    const int o = gid >> 6;
    const int b = gid & 63;
    const float* p = g_part + (size_t)o * BATCH + b;

    float a0 = 0.f, a1 = 0.f, a2 = 0.f, a3 = 0.f;
#pragma unroll
    for (int kzi = 0; kzi < SPLITS; kzi += 4) {
        a0 += p[(size_t)(kzi + 0) * (OUTF * BATCH)];
        a1 += p[(size_t)(kzi + 1) * (OUTF * BATCH)];
        a2 += p[(size_t)(kzi + 2) * (OUTF * BATCH)];
        a3 += p[(size_t)(kzi + 3) * (OUTF * BATCH)];
    }
    y[(size_t)b * OUTF + o] = (a0 + a1) + (a2 + a3);
}

// ---------------------------------------------------------------------------
extern "C" void kernel_launch(void* const* d_in, const int* in_sizes, int n_in,
                              void* d_out, int out_size)
{
    (void)in_sizes; (void)n_in; (void)out_size;
    const float* x          = (const float*)d_in[0];
    const float* weight     = (const float*)d_in[1];
    const float* align_conv = (const float*)d_in[2];
    const float* W_ih       = (const float*)d_in[3];
    // d_in[4] = W_hh : unused (h0 == 0)
    const float* b_ih       = (const float*)d_in[5];
    const float* b_hh       = (const float*)d_in[6];
    const float* W_att      = (const float*)d_in[7];
    const float* b_att      = (const float*)d_in[8];
    float* y = (float*)d_out;

    static bool attr_set = false;
    if (!attr_set) {
        cudaFuncSetAttribute(gemm_hmma,
                             cudaFuncAttributeMaxDynamicSharedMemorySize,
                             SMEM_DYN);
        attr_set = true;
    }

    gate_kernel<<<BATCH, 256>>>(x, align_conv, W_ih, b_ih, b_hh, W_att, b_att);
    gemm_hmma<<<dim3(OUTF / 128, SPLITS), 256, SMEM_DYN>>>(x, weight);
    reduce_kernel<<<(OUTF * BATCH) / 256, 256>>>(y);
}